// round 5
// baseline (speedup 1.0000x reference)
#include <cuda_runtime.h>
#include <math.h>
#include <stdint.h>

#define B_  2
#define T_  2048
#define D_  2048
#define NH_ 16
#define KH_ 4
#define H_  128

// Scratch (allocation-free rule: __device__ globals)
__device__ float    g_q[B_*T_*NH_*H_];     // q proj (fp32 from gemm) -> tf32 bits after rope (in place)
__device__ float    g_k[B_*T_*KH_*H_];     // k proj fp32
__device__ uint32_t g_k2[B_*T_*KH_*H_];    // k rope'd, h-permuted, tf32 bits
__device__ float    g_v[B_*T_*KH_*H_];     // v proj fp32 -> tf32 bits (in place)
__device__ uint32_t g_attn[B_*T_*NH_*H_];  // attn out, tf32 bits
__device__ uint32_t g_xq[B_*T_*D_];        // Xq  tf32 bits
__device__ uint32_t g_xkv[B_*T_*D_];       // Xkv tf32 bits
__device__ uint32_t g_wq[D_*NH_*H_];
__device__ uint32_t g_wk[D_*KH_*H_];
__device__ uint32_t g_wv[D_*KH_*H_];
__device__ uint32_t g_wo[NH_*H_*D_];

__device__ __forceinline__ uint32_t f2tf32(float f) {
    uint32_t u;
    asm("cvt.rna.tf32.f32 %0, %1;" : "=r"(u) : "f"(f));
    return u;
}

__device__ __forceinline__ void cpasync16(void* dst, const void* src) {
    uint32_t d = (uint32_t)__cvta_generic_to_shared(dst);
    asm volatile("cp.async.cg.shared.global [%0], [%1], 16;\n" :: "r"(d), "l"(src));
}

__device__ __forceinline__ void mma_tf32(float* c, const uint32_t* a, const uint32_t* b) {
    asm volatile(
        "mma.sync.aligned.m16n8k8.row.col.f32.tf32.tf32.f32 "
        "{%0,%1,%2,%3}, {%4,%5,%6,%7}, {%8,%9}, {%0,%1,%2,%3};\n"
        : "+f"(c[0]), "+f"(c[1]), "+f"(c[2]), "+f"(c[3])
        : "r"(a[0]), "r"(a[1]), "r"(a[2]), "r"(a[3]),
          "r"(b[0]), "r"(b[1]));
}

// fp32 -> tf32 bits, out of place
__global__ void cvt_to_kernel(const float* __restrict__ src, uint32_t* __restrict__ dst) {
    int i = blockIdx.x * 256 + threadIdx.x;
    float4 v = ((const float4*)src)[i];
    ((uint4*)dst)[i] = make_uint4(f2tf32(v.x), f2tf32(v.y), f2tf32(v.z), f2tf32(v.w));
}

// fp32 -> tf32 bits, in place (V)
__global__ void cvt_tf32_kernel(float* __restrict__ x) {
    int i = blockIdx.x * 256 + threadIdx.x;
    float4 vv = ((const float4*)x)[i];
    ((uint4*)x)[i] = make_uint4(f2tf32(vv.x), f2tf32(vv.y), f2tf32(vv.z), f2tf32(vv.w));
}

// ---------------------------------------------------------------------------
// TF32 tensor-core GEMM on pre-converted tf32-bit operands (no cvt in loop).
// ---------------------------------------------------------------------------
#define AST 20
#define BST 132

__device__ __forceinline__
void gemm_body(const uint32_t* __restrict__ A, const uint32_t* __restrict__ B,
               float* __restrict__ C, int M, int Nc, int Kd) {
    __shared__ uint32_t As[2][128 * AST];
    __shared__ uint32_t Bs[2][16 * BST];
    int tid  = threadIdx.x;
    int brow = blockIdx.y * 128, bcol = blockIdx.x * 128;
    int warp = tid >> 5, lane = tid & 31;
    int mw = (warp >> 2) * 64, nw = (warp & 3) * 32;
    int lr = lane >> 2, lc = lane & 3;

    float acc[4][4][4];
#pragma unroll
    for (int mi = 0; mi < 4; mi++)
#pragma unroll
        for (int ni = 0; ni < 4; ni++)
#pragma unroll
            for (int j = 0; j < 4; j++) acc[mi][ni][j] = 0.f;

    const int nkt = Kd >> 4;

    auto load_stage = [&](int kt, int buf) {
        int k0 = kt * 16;
#pragma unroll
        for (int u = 0; u < 2; u++) {
            int c = tid + 256 * u;
            int arow = c >> 2, ak4 = (c & 3) * 4;
            cpasync16(&As[buf][arow * AST + ak4],
                      &A[(size_t)(brow + arow) * Kd + k0 + ak4]);
            int bkr = c >> 5, bn4 = (c & 31) * 4;
            cpasync16(&Bs[buf][bkr * BST + bn4],
                      &B[(size_t)(k0 + bkr) * Nc + bcol + bn4]);
        }
    };

    load_stage(0, 0);
    asm volatile("cp.async.commit_group;\n");

    for (int kt = 0; kt < nkt; kt++) {
        int buf = kt & 1;
        if (kt + 1 < nkt) {
            load_stage(kt + 1, buf ^ 1);
            asm volatile("cp.async.commit_group;\n");
            asm volatile("cp.async.wait_group 1;\n");
        } else {
            asm volatile("cp.async.wait_group 0;\n");
        }
        __syncthreads();

#pragma unroll
        for (int ks = 0; ks < 16; ks += 8) {
            uint32_t af[4][4], bf[4][2];
#pragma unroll
            for (int mi = 0; mi < 4; mi++) {
                const uint32_t* p = &As[buf][(mw + mi * 16 + lr) * AST + ks + lc];
                af[mi][0] = p[0];
                af[mi][1] = p[8 * AST];
                af[mi][2] = p[4];
                af[mi][3] = p[8 * AST + 4];
            }
#pragma unroll
            for (int ni = 0; ni < 4; ni++) {
                const uint32_t* p = &Bs[buf][(ks + lc) * BST + nw + ni * 8 + lr];
                bf[ni][0] = p[0];
                bf[ni][1] = p[4 * BST];
            }
#pragma unroll
            for (int mi = 0; mi < 4; mi++)
#pragma unroll
                for (int ni = 0; ni < 4; ni++)
                    mma_tf32(acc[mi][ni], af[mi], bf[ni]);
        }
        __syncthreads();
    }

#pragma unroll
    for (int mi = 0; mi < 4; mi++) {
#pragma unroll
        for (int ni = 0; ni < 4; ni++) {
            int r0 = brow + mw + mi * 16 + lr;
            int cc = bcol + nw + ni * 8 + lc * 2;
            *(float2*)&C[(size_t)r0 * Nc + cc] =
                make_float2(acc[mi][ni][0], acc[mi][ni][1]);
            *(float2*)&C[(size_t)(r0 + 8) * Nc + cc] =
                make_float2(acc[mi][ni][2], acc[mi][ni][3]);
        }
    }
}

__global__ __launch_bounds__(256)
void gemm_raw(const uint32_t* __restrict__ A, const uint32_t* __restrict__ B,
              float* __restrict__ C, int M, int Nc, int Kd) {
    gemm_body(A, B, C, M, Nc, Kd);
}

__global__ __launch_bounds__(256)
void gemm_raw_kv(const uint32_t* __restrict__ A,
                 const uint32_t* __restrict__ B0, const uint32_t* __restrict__ B1,
                 float* __restrict__ C0, float* __restrict__ C1,
                 int M, int Nc, int Kd) {
    gemm_body(A, blockIdx.z ? B1 : B0, blockIdx.z ? C1 : C0, M, Nc, Kd);
}

// ---------------------------------------------------------------------------
// RoPE variants
// ---------------------------------------------------------------------------
// Q: in-place rope + scale + tf32-bit cvt (linear layout)
__global__ void rope_q_kernel(float* __restrict__ x, const int* __restrict__ pos,
                              float scale) {
    int token = blockIdx.x;
    int i = threadIdx.x;  // 0..63
    double ts = exp(((double)i / 64.0) * 9.210340371976182736);
    float p = (float)pos[token];
    float angf = p / (float)ts;
    double s_, c_;
    sincos((double)angf, &s_, &c_);
    float s = (float)s_, c = (float)c_;
    float* base = x + (size_t)token * NH_ * H_;
    uint32_t* baseb = (uint32_t*)base;
#pragma unroll 4
    for (int n = 0; n < NH_; n++) {
        float x1 = base[n * H_ + i];
        float x2 = base[n * H_ + i + 64];
        baseb[n * H_ + i]      = f2tf32((x1 * c - x2 * s) * scale);
        baseb[n * H_ + i + 64] = f2tf32((x2 * c + x1 * s) * scale);
    }
}

// K: out-of-place rope + tf32 cvt + within-8 h permutation (e -> 2*(e&3) + (e>>2))
__device__ __forceinline__ int permh(int j) {
    return (j & ~7) + ((j & 3) * 2 + ((j & 7) >> 2));
}

__global__ void rope_k_kernel(const float* __restrict__ x, uint32_t* __restrict__ y,
                              const int* __restrict__ pos) {
    int token = blockIdx.x;
    int i = threadIdx.x;  // 0..63
    double ts = exp(((double)i / 64.0) * 9.210340371976182736);
    float p = (float)pos[token];
    float angf = p / (float)ts;
    double s_, c_;
    sincos((double)angf, &s_, &c_);
    float s = (float)s_, c = (float)c_;
    const float* base = x + (size_t)token * KH_ * H_;
    uint32_t* dst = y + (size_t)token * KH_ * H_;
    int p1 = permh(i), p2 = permh(i + 64);
#pragma unroll
    for (int n = 0; n < KH_; n++) {
        float x1 = base[n * H_ + i];
        float x2 = base[n * H_ + i + 64];
        dst[n * H_ + p1] = f2tf32(x1 * c - x2 * s);
        dst[n * H_ + p2] = f2tf32(x2 * c + x1 * s);
    }
}

// ---------------------------------------------------------------------------
// Tensor-core flash attention (tf32 bits), causal, GQA.
// K gmem is h-permuted so each QK B-fragment is one uint2 LDS.
// FST=136 keeps the 8B fragment loads phase-conflict-free.
// ---------------------------------------------------------------------------
#define FST 136
#define VST 136
#define PST 68
#define FA4_SMEM ((2*64*FST + 2*64*VST + 8*16*PST) * 4)

__global__ __launch_bounds__(256, 1)
void flash_tc(const uint32_t* __restrict__ q, const uint32_t* __restrict__ k,
              const uint32_t* __restrict__ v, uint32_t* __restrict__ o) {
    extern __shared__ uint32_t sm_u[];
    uint32_t* Ks = sm_u;                    // [2][64*FST]
    uint32_t* Vs = Ks + 2 * 64 * FST;       // [2][64*VST]
    uint32_t* Ps = Vs + 2 * 64 * VST;       // 8 warps x 16 x PST

    int qt = (int)gridDim.x - 1 - (int)blockIdx.x;  // big tiles first
    int n  = blockIdx.y;
    int b  = blockIdx.z;
    int kh = n >> 2;
    int tid = threadIdx.x, warp = tid >> 5, lane = tid & 31;
    int lr = lane >> 2, lc = lane & 3;
    int q0 = qt * 128;

    // ---- load Q fragments (two staging passes through Ks[0], raw bits) ----
    uint32_t qf[16][4];
#pragma unroll
    for (int pass = 0; pass < 2; pass++) {
#pragma unroll
        for (int u = 0; u < 8; u++) {
            int f = tid + 256 * u;
            int r = f >> 5, hc = (f & 31) * 4;
            *(uint4*)(Ks + r * FST + hc) = *(const uint4*)(q +
                (((size_t)(b * T_ + q0 + pass * 64 + r) * NH_ + n) << 7) + hc);
        }
        __syncthreads();
        if ((warp >> 2) == pass) {
            int mr = (warp & 3) * 16;
#pragma unroll
            for (int hs = 0; hs < 16; hs++) {
                const uint32_t* p = Ks + (mr + lr) * FST + hs * 8 + lc;
                qf[hs][0] = p[0];
                qf[hs][1] = p[8 * FST];
                qf[hs][2] = p[4];
                qf[hs][3] = p[8 * FST + 4];
            }
        }
        __syncthreads();
    }

    float m_[2] = {-1e30f, -1e30f};
    float l_[2] = {0.f, 0.f};
    float oacc[16][4];
#pragma unroll
    for (int ns = 0; ns < 16; ns++)
#pragma unroll
        for (int j = 0; j < 4; j++) oacc[ns][j] = 0.f;

    int row0 = q0 + warp * 16 + lr;
    int njt = 2 * qt + 2;

    auto load_kv = [&](int jt, int bufsel) {
        int s0 = jt * 64;
        uint32_t* Kd = Ks + bufsel * 64 * FST;
        uint32_t* Vd = Vs + bufsel * 64 * VST;
#pragma unroll
        for (int u = 0; u < 8; u++) {
            int f = tid + 256 * u;
            int r = f >> 5, hc = (f & 31) * 4;
            size_t gofs = (((size_t)(b * T_ + s0 + r) * KH_ + kh) << 7) + hc;
            cpasync16(Kd + r * FST + hc, k + gofs);
            cpasync16(Vd + r * VST + hc, v + gofs);
        }
    };

    load_kv(0, 0);
    asm volatile("cp.async.commit_group;\n");

    for (int jt = 0; jt < njt; jt++) {
        int buf = jt & 1;
        if (jt + 1 < njt) {
            load_kv(jt + 1, buf ^ 1);
            asm volatile("cp.async.commit_group;\n");
            asm volatile("cp.async.wait_group 1;\n");
        } else {
            asm volatile("cp.async.wait_group 0;\n");
        }
        __syncthreads();

        const uint32_t* Kb = Ks + buf * 64 * FST;
        const uint32_t* Vb = Vs + buf * 64 * VST;
        int s0 = jt * 64;

        // ---- S = Q K^T (K h-paired: one uint2 per B-fragment) ----
        float s_[8][4];
#pragma unroll
        for (int ns = 0; ns < 8; ns++)
#pragma unroll
            for (int j = 0; j < 4; j++) s_[ns][j] = 0.f;
#pragma unroll
        for (int hs = 0; hs < 16; hs++) {
#pragma unroll
            for (int ns = 0; ns < 8; ns++) {
                uint2 bv = *(const uint2*)(Kb + (ns * 8 + lr) * FST + hs * 8 + 2 * lc);
                uint32_t bf[2] = {bv.x, bv.y};
                mma_tf32(s_[ns], qf[hs], bf);
            }
        }

        // ---- causal mask (only last two kv tiles cross the diagonal) ----
        if (jt >= 2 * qt) {
#pragma unroll
            for (int ns = 0; ns < 8; ns++) {
                int col = s0 + ns * 8 + 2 * lc;
                if (col > row0)     s_[ns][0] = -1e30f;
                if (col + 1 > row0) s_[ns][1] = -1e30f;
                if (col > row0 + 8)     s_[ns][2] = -1e30f;
                if (col + 1 > row0 + 8) s_[ns][3] = -1e30f;
            }
        }

        // ---- online softmax in registers ----
        float mx0 = -1e30f, mx1 = -1e30f;
#pragma unroll
        for (int ns = 0; ns < 8; ns++) {
            mx0 = fmaxf(mx0, fmaxf(s_[ns][0], s_[ns][1]));
            mx1 = fmaxf(mx1, fmaxf(s_[ns][2], s_[ns][3]));
        }
        mx0 = fmaxf(mx0, __shfl_xor_sync(0xffffffffu, mx0, 1));
        mx0 = fmaxf(mx0, __shfl_xor_sync(0xffffffffu, mx0, 2));
        mx1 = fmaxf(mx1, __shfl_xor_sync(0xffffffffu, mx1, 1));
        mx1 = fmaxf(mx1, __shfl_xor_sync(0xffffffffu, mx1, 2));
        float mn0 = fmaxf(m_[0], mx0), mn1 = fmaxf(m_[1], mx1);
        float a0 = __expf(m_[0] - mn0), a1 = __expf(m_[1] - mn1);
        float sum0 = 0.f, sum1 = 0.f;
        uint32_t* Pw = Ps + warp * 16 * PST;
#pragma unroll
        for (int ns = 0; ns < 8; ns++) {
            float p0 = __expf(s_[ns][0] - mn0);
            float p1 = __expf(s_[ns][1] - mn0);
            float p2 = __expf(s_[ns][2] - mn1);
            float p3 = __expf(s_[ns][3] - mn1);
            sum0 += p0 + p1;
            sum1 += p2 + p3;
            *(uint2*)(Pw + lr * PST + ns * 8 + 2 * lc) =
                make_uint2(f2tf32(p0), f2tf32(p1));
            *(uint2*)(Pw + (lr + 8) * PST + ns * 8 + 2 * lc) =
                make_uint2(f2tf32(p2), f2tf32(p3));
        }
        sum0 += __shfl_xor_sync(0xffffffffu, sum0, 1);
        sum0 += __shfl_xor_sync(0xffffffffu, sum0, 2);
        sum1 += __shfl_xor_sync(0xffffffffu, sum1, 1);
        sum1 += __shfl_xor_sync(0xffffffffu, sum1, 2);
        l_[0] = l_[0] * a0 + sum0;
        l_[1] = l_[1] * a1 + sum1;
        m_[0] = mn0; m_[1] = mn1;

#pragma unroll
        for (int ns = 0; ns < 16; ns++) {
            oacc[ns][0] *= a0; oacc[ns][1] *= a0;
            oacc[ns][2] *= a1; oacc[ns][3] *= a1;
        }
        __syncwarp();

        // ---- O += P V ----
#pragma unroll
        for (int ks = 0; ks < 8; ks++) {
            const uint32_t* pp = Pw + lr * PST + ks * 8 + lc;
            uint32_t af[4] = {pp[0], pp[8 * PST], pp[4], pp[8 * PST + 4]};
#pragma unroll
            for (int ns = 0; ns < 16; ns++) {
                const uint32_t* vp = Vb + (ks * 8 + lc) * VST + ns * 8 + lr;
                uint32_t bf[2] = {vp[0], vp[4 * VST]};
                mma_tf32(oacc[ns], af, bf);
            }
        }
        __syncthreads();
    }

    // ---- epilogue: normalize + store tf32 bits (b,t,n,h) ----
    float inv0 = 1.f / l_[0], inv1 = 1.f / l_[1];
    size_t base0 = (((size_t)(b * T_ + row0) * NH_ + n) << 7);
    size_t base1 = (((size_t)(b * T_ + row0 + 8) * NH_ + n) << 7);
#pragma unroll
    for (int ns = 0; ns < 16; ns++) {
        int cc = ns * 8 + 2 * lc;
        *(uint2*)(o + base0 + cc) =
            make_uint2(f2tf32(oacc[ns][0] * inv0), f2tf32(oacc[ns][1] * inv0));
        *(uint2*)(o + base1 + cc) =
            make_uint2(f2tf32(oacc[ns][2] * inv1), f2tf32(oacc[ns][3] * inv1));
    }
}

// ---------------------------------------------------------------------------
extern "C" void kernel_launch(void* const* d_in, const int* in_sizes, int n_in,
                              void* d_out, int out_size) {
    const float* Xq   = (const float*)d_in[0];
    const float* Xkv  = (const float*)d_in[1];
    const int*   qpos = (const int*)  d_in[2];
    const int*   kpos = (const int*)  d_in[3];
    const float* Wq   = (const float*)d_in[4];
    const float* Wk   = (const float*)d_in[5];
    const float* Wv   = (const float*)d_in[6];
    const float* Wo   = (const float*)d_in[7];
    float* out = (float*)d_out;

    float *pq, *pk, *pv;
    uint32_t *pk2, *pa, *pxq, *pxkv, *pwq, *pwk, *pwv, *pwo;
    cudaGetSymbolAddress((void**)&pq,  g_q);
    cudaGetSymbolAddress((void**)&pk,  g_k);
    cudaGetSymbolAddress((void**)&pk2, g_k2);
    cudaGetSymbolAddress((void**)&pv,  g_v);
    cudaGetSymbolAddress((void**)&pa,  g_attn);
    cudaGetSymbolAddress((void**)&pxq, g_xq);
    cudaGetSymbolAddress((void**)&pxkv,g_xkv);
    cudaGetSymbolAddress((void**)&pwq, g_wq);
    cudaGetSymbolAddress((void**)&pwk, g_wk);
    cudaGetSymbolAddress((void**)&pwv, g_wv);
    cudaGetSymbolAddress((void**)&pwo, g_wo);

    const int M = B_ * T_;  // 4096
    const float scale = 0.08838834764831845f; // 1/sqrt(128)

    // pre-convert all GEMM operands to tf32 bits
    cvt_to_kernel<<<(B_*T_*D_) / 1024, 256>>>(Xq,  pxq);
    cvt_to_kernel<<<(B_*T_*D_) / 1024, 256>>>(Xkv, pxkv);
    cvt_to_kernel<<<(D_*NH_*H_) / 1024, 256>>>(Wq, pwq);
    cvt_to_kernel<<<(D_*KH_*H_) / 1024, 256>>>(Wk, pwk);
    cvt_to_kernel<<<(D_*KH_*H_) / 1024, 256>>>(Wv, pwv);
    cvt_to_kernel<<<(NH_*H_*D_) / 1024, 256>>>(Wo, pwo);

    // projections (raw tf32-bit operands)
    gemm_raw<<<dim3(D_ / 128, M / 128), 256>>>(pxq, pwq, pq, M, NH_ * H_, D_);
    gemm_raw_kv<<<dim3((KH_ * H_) / 128, M / 128, 2), 256>>>(
        pxkv, pwk, pwv, pk, pv, M, KH_ * H_, D_);

    // rope + conversions
    rope_q_kernel<<<M, 64>>>(pq, qpos, scale);
    rope_k_kernel<<<M, 64>>>(pk, pk2, kpos);
    cvt_tf32_kernel<<<(B_*T_*KH_*H_) / 1024, 256>>>(pv);

    // flash attention (tensor core, double-buffered, paired-K)
    cudaFuncSetAttribute(flash_tc,
                         cudaFuncAttributeMaxDynamicSharedMemorySize, FA4_SMEM);
    flash_tc<<<dim3(T_ / 128, NH_, B_), 256, FA4_SMEM>>>(
        (const uint32_t*)pq, pk2, (const uint32_t*)pv, pa);

    // output projection
    gemm_raw<<<dim3(D_ / 128, M / 128), 256>>>(pa, pwo, out, M, D_, NH_ * H_);
}

// round 6
// speedup vs baseline: 1.7108x; 1.7108x over previous
#include <cuda_runtime.h>
#include <cuda_fp16.h>
#include <math.h>
#include <stdint.h>

#define B_  2
#define T_  2048
#define D_  2048
#define NH_ 16
#define KH_ 4
#define H_  128

// Scratch (allocation-free rule: __device__ globals)
__device__ __half g_xqh [B_*T_*D_];        // Xq  fp16
__device__ __half g_xkvh[B_*T_*D_];        // Xkv fp16
__device__ __half g_wqt [NH_*H_*D_];       // Wq^T  fp16 [NHH][D]
__device__ __half g_wkt [KH_*H_*D_];       // Wk^T  fp16 [KHH][D]
__device__ __half g_wvt [KH_*H_*D_];       // Wv^T  fp16 [KHH][D]
__device__ __half g_wot [D_*NH_*H_];       // Wo^T  fp16 [D][NHH]
__device__ float  g_q  [B_*T_*NH_*H_];     // q proj fp32
__device__ float  g_k  [B_*T_*KH_*H_];     // k proj fp32
__device__ float  g_v  [B_*T_*KH_*H_];     // v proj fp32
__device__ __half g_qh [B_*T_*NH_*H_];     // q rope'd, scaled, fp16 (b,t,n,h)
__device__ __half g_kh [B_*T_*KH_*H_];     // k rope'd fp16 (b,t,k,h)
__device__ __half g_vt [B_*KH_*H_*T_];     // v fp16 transposed (b,k,h,t)
__device__ __half g_attn[B_*T_*NH_*H_];    // attn out fp16 (b,t,n,h)

__device__ __forceinline__ uint32_t f2h2(float lo, float hi) {
    __half2 h = __floats2half2_rn(lo, hi);
    return *(uint32_t*)&h;
}

__device__ __forceinline__ void cpasync16(void* dst, const void* src) {
    uint32_t d = (uint32_t)__cvta_generic_to_shared(dst);
    asm volatile("cp.async.cg.shared.global [%0], [%1], 16;\n" :: "r"(d), "l"(src));
}

__device__ __forceinline__ void mma16(float* c, const uint32_t* a, const uint32_t* b) {
    asm volatile(
        "mma.sync.aligned.m16n8k16.row.col.f32.f16.f16.f32 "
        "{%0,%1,%2,%3}, {%4,%5,%6,%7}, {%8,%9}, {%0,%1,%2,%3};\n"
        : "+f"(c[0]), "+f"(c[1]), "+f"(c[2]), "+f"(c[3])
        : "r"(a[0]), "r"(a[1]), "r"(a[2]), "r"(a[3]),
          "r"(b[0]), "r"(b[1]));
}

// ---------------------------------------------------------------------------
// Aux kernels: cvt fp32->fp16, transposes
// ---------------------------------------------------------------------------
__global__ void cvt16(const float* __restrict__ s, __half2* __restrict__ d) {
    int i = blockIdx.x * 256 + threadIdx.x;
    float4 a = ((const float4*)s)[i];
    d[2*i]   = __floats2half2_rn(a.x, a.y);
    d[2*i+1] = __floats2half2_rn(a.z, a.w);
}

// transpose + cvt: src fp32 [R][C] -> dst fp16 [C][R]; grid (C/32, R/32), 256 thr
__global__ void tr16(const float* __restrict__ src, __half* __restrict__ dst,
                     int R, int C) {
    __shared__ float tile[32][33];
    int c0 = blockIdx.x * 32, r0 = blockIdx.y * 32;
    int tx = threadIdx.x & 31, ty = threadIdx.x >> 5;
#pragma unroll
    for (int i = 0; i < 32; i += 8)
        tile[ty + i][tx] = src[(size_t)(r0 + ty + i) * C + c0 + tx];
    __syncthreads();
#pragma unroll
    for (int i = 0; i < 32; i += 8)
        dst[(size_t)(c0 + ty + i) * R + r0 + tx] = __float2half_rn(tile[tx][ty + i]);
}

// V transpose: fp32 (b,t,kh,h) -> fp16 (b,kh,h,t); grid (T/32, H/32, B*KH)
__global__ void trv(const float* __restrict__ v, __half* __restrict__ vt) {
    __shared__ float tile[32][33];
    int bk = blockIdx.z, b = bk >> 2, kh = bk & 3;
    int t0 = blockIdx.x * 32, h0 = blockIdx.y * 32;
    int tx = threadIdx.x & 31, ty = threadIdx.x >> 5;
#pragma unroll
    for (int i = 0; i < 32; i += 8)
        tile[ty + i][tx] =
            v[(((size_t)(b * T_ + t0 + ty + i)) * KH_ + kh) * H_ + h0 + tx];
    __syncthreads();
#pragma unroll
    for (int i = 0; i < 32; i += 8)
        vt[((size_t)(b * KH_ + kh) * H_ + h0 + ty + i) * T_ + t0 + tx] =
            __float2half_rn(tile[tx][ty + i]);
}

// ---------------------------------------------------------------------------
// RoPE: fp32 in -> fp16 out (q also scaled)
// ---------------------------------------------------------------------------
__global__ void rope_q16(const float* __restrict__ x, __half* __restrict__ y,
                         const int* __restrict__ pos, float scale) {
    int token = blockIdx.x;
    int i = threadIdx.x;  // 0..63
    double ts = exp(((double)i / 64.0) * 9.210340371976182736);
    float p = (float)pos[token];
    float angf = p / (float)ts;
    double s_, c_;
    sincos((double)angf, &s_, &c_);
    float s = (float)s_, c = (float)c_;
    const float* base = x + (size_t)token * NH_ * H_;
    __half* dst = y + (size_t)token * NH_ * H_;
#pragma unroll 4
    for (int n = 0; n < NH_; n++) {
        float x1 = base[n * H_ + i];
        float x2 = base[n * H_ + i + 64];
        dst[n * H_ + i]      = __float2half_rn((x1 * c - x2 * s) * scale);
        dst[n * H_ + i + 64] = __float2half_rn((x2 * c + x1 * s) * scale);
    }
}

__global__ void rope_k16(const float* __restrict__ x, __half* __restrict__ y,
                         const int* __restrict__ pos) {
    int token = blockIdx.x;
    int i = threadIdx.x;
    double ts = exp(((double)i / 64.0) * 9.210340371976182736);
    float p = (float)pos[token];
    float angf = p / (float)ts;
    double s_, c_;
    sincos((double)angf, &s_, &c_);
    float s = (float)s_, c = (float)c_;
    const float* base = x + (size_t)token * KH_ * H_;
    __half* dst = y + (size_t)token * KH_ * H_;
#pragma unroll
    for (int n = 0; n < KH_; n++) {
        float x1 = base[n * H_ + i];
        float x2 = base[n * H_ + i + 64];
        dst[n * H_ + i]      = __float2half_rn(x1 * c - x2 * s);
        dst[n * H_ + i + 64] = __float2half_rn(x2 * c + x1 * s);
    }
}

// ---------------------------------------------------------------------------
// FP16 tensor-core GEMM: C[M,Nc]fp32 = A[M,Kd]fp16 @ Bt[Nc,Kd]fp16^T
// 128x128 tile, k-tile 32, m16n8k16, cp.async double buffered.
// Smem rows: 16 words (32 halves) + 4 pad = stride 20 (conflict-free frags).
// ---------------------------------------------------------------------------
#define GST 20

__device__ __forceinline__
void gemm16_body(const uint32_t* __restrict__ A, const uint32_t* __restrict__ Bt,
                 float* __restrict__ C, int M, int Nc, int Kd) {
    __shared__ uint32_t As[2][128 * GST];
    __shared__ uint32_t Bs[2][128 * GST];
    int tid  = threadIdx.x;
    int brow = blockIdx.y * 128, bcol = blockIdx.x * 128;
    int warp = tid >> 5, lane = tid & 31;
    int mw = (warp >> 2) * 64, nw = (warp & 3) * 32;
    int lr = lane >> 2, lc = lane & 3;
    int KW = Kd >> 1;  // words per row

    float acc[4][4][4];
#pragma unroll
    for (int mi = 0; mi < 4; mi++)
#pragma unroll
        for (int ni = 0; ni < 4; ni++)
#pragma unroll
            for (int j = 0; j < 4; j++) acc[mi][ni][j] = 0.f;

    const int nkt = Kd >> 5;

    auto load_stage = [&](int kt, int buf) {
        int kw0 = kt * 16;
#pragma unroll
        for (int u = 0; u < 2; u++) {
            int c = tid + 256 * u;
            int row = c >> 2, w4 = (c & 3) * 4;
            cpasync16(&As[buf][row * GST + w4],
                      &A[(size_t)(brow + row) * KW + kw0 + w4]);
            cpasync16(&Bs[buf][row * GST + w4],
                      &Bt[(size_t)(bcol + row) * KW + kw0 + w4]);
        }
    };

    load_stage(0, 0);
    asm volatile("cp.async.commit_group;\n");

    for (int kt = 0; kt < nkt; kt++) {
        int buf = kt & 1;
        if (kt + 1 < nkt) {
            load_stage(kt + 1, buf ^ 1);
            asm volatile("cp.async.commit_group;\n");
            asm volatile("cp.async.wait_group 1;\n");
        } else {
            asm volatile("cp.async.wait_group 0;\n");
        }
        __syncthreads();

#pragma unroll
        for (int ks = 0; ks < 2; ks++) {
            uint32_t af[4][4], bf[4][2];
#pragma unroll
            for (int mi = 0; mi < 4; mi++) {
                const uint32_t* p = &As[buf][(mw + mi * 16 + lr) * GST + ks * 8 + lc];
                af[mi][0] = p[0];
                af[mi][1] = p[8 * GST];
                af[mi][2] = p[4];
                af[mi][3] = p[8 * GST + 4];
            }
#pragma unroll
            for (int ni = 0; ni < 4; ni++) {
                const uint32_t* p = &Bs[buf][(nw + ni * 8 + lr) * GST + ks * 8 + lc];
                bf[ni][0] = p[0];
                bf[ni][1] = p[4];
            }
#pragma unroll
            for (int mi = 0; mi < 4; mi++)
#pragma unroll
                for (int ni = 0; ni < 4; ni++)
                    mma16(acc[mi][ni], af[mi], bf[ni]);
        }
        __syncthreads();
    }

#pragma unroll
    for (int mi = 0; mi < 4; mi++) {
#pragma unroll
        for (int ni = 0; ni < 4; ni++) {
            int r0 = brow + mw + mi * 16 + lr;
            int cc = bcol + nw + ni * 8 + lc * 2;
            *(float2*)&C[(size_t)r0 * Nc + cc] =
                make_float2(acc[mi][ni][0], acc[mi][ni][1]);
            *(float2*)&C[(size_t)(r0 + 8) * Nc + cc] =
                make_float2(acc[mi][ni][2], acc[mi][ni][3]);
        }
    }
}

__global__ __launch_bounds__(256)
void gemm16(const uint32_t* __restrict__ A, const uint32_t* __restrict__ Bt,
            float* __restrict__ C, int M, int Nc, int Kd) {
    gemm16_body(A, Bt, C, M, Nc, Kd);
}

__global__ __launch_bounds__(256)
void gemm16_kv(const uint32_t* __restrict__ A,
               const uint32_t* __restrict__ B0, const uint32_t* __restrict__ B1,
               float* __restrict__ C0, float* __restrict__ C1,
               int M, int Nc, int Kd) {
    gemm16_body(A, blockIdx.z ? B1 : B0, blockIdx.z ? C1 : C0, M, Nc, Kd);
}

// ---------------------------------------------------------------------------
// FP16 tensor-core flash attention, causal, GQA.
// Q tile 128 (8 warps x m16), KV tile 64, m16n8k16, cp.async double buffer.
// Ks [64][68w], Vs(=V^T) [128][36w], Ps [8][16][36w] — all conflict-free.
// ---------------------------------------------------------------------------
#define KST  68
#define VSTW 36
#define PSTW 36
#define FA5_SMEM ((2*64*KST + 2*128*VSTW + 8*16*PSTW) * 4)

__global__ __launch_bounds__(256, 1)
void flash16(const uint32_t* __restrict__ qh, const uint32_t* __restrict__ kk,
             const uint32_t* __restrict__ vt, uint32_t* __restrict__ o) {
    extern __shared__ uint32_t sm_u[];
    uint32_t* Ks = sm_u;                     // [2][64*KST]
    uint32_t* Vs = Ks + 2 * 64 * KST;        // [2][128*VSTW]
    uint32_t* Ps = Vs + 2 * 128 * VSTW;      // [8][16*PSTW]

    int qt = (int)gridDim.x - 1 - (int)blockIdx.x;  // big tiles first
    int n  = blockIdx.y;
    int b  = blockIdx.z;
    int khd = n >> 2;
    int tid = threadIdx.x, warp = tid >> 5, lane = tid & 31;
    int lr = lane >> 2, lc = lane & 3;
    int q0 = qt * 128;

    // ---- Q fragments: stage 64 rows at a time into Ks[0], frag-load ----
    uint32_t qf[8][4];
#pragma unroll
    for (int pass = 0; pass < 2; pass++) {
#pragma unroll
        for (int u = 0; u < 4; u++) {
            int f = tid + 256 * u;
            int r = f >> 4, w4 = (f & 15) * 4;
            *(uint4*)(Ks + r * KST + w4) = *(const uint4*)(qh +
                ((size_t)((b * T_ + q0 + pass * 64 + r) * NH_ + n) << 6) + w4);
        }
        __syncthreads();
        if ((warp >> 2) == pass) {
            int mr = (warp & 3) * 16;
#pragma unroll
            for (int hs = 0; hs < 8; hs++) {
                const uint32_t* p = Ks + (mr + lr) * KST + hs * 8 + lc;
                qf[hs][0] = p[0];
                qf[hs][1] = p[8 * KST];
                qf[hs][2] = p[4];
                qf[hs][3] = p[8 * KST + 4];
            }
        }
        __syncthreads();
    }

    float m_[2] = {-1e30f, -1e30f};
    float l_[2] = {0.f, 0.f};
    float oacc[16][4];
#pragma unroll
    for (int ns = 0; ns < 16; ns++)
#pragma unroll
        for (int j = 0; j < 4; j++) oacc[ns][j] = 0.f;

    int row0 = q0 + warp * 16 + lr;
    int njt = 2 * qt + 2;

    auto load_kv = [&](int jt, int bufsel) {
        int s0 = jt * 64;
        uint32_t* Kd = Ks + bufsel * 64 * KST;
        uint32_t* Vd = Vs + bufsel * 128 * VSTW;
#pragma unroll
        for (int u = 0; u < 4; u++) {
            int f = tid + 256 * u;
            int r = f >> 4, w4 = (f & 15) * 4;           // K: 64 rows x 16 w4
            cpasync16(Kd + r * KST + w4,
                      kk + ((size_t)((b * T_ + s0 + r) * KH_ + khd) << 6) + w4);
            int hrow = f >> 3, vw4 = (f & 7) * 4;        // V^T: 128 rows x 8 w4
            cpasync16(Vd + hrow * VSTW + vw4,
                      vt + ((((size_t)(b * KH_ + khd) * H_ + hrow) * T_ + s0) >> 1) + vw4);
        }
    };

    load_kv(0, 0);
    asm volatile("cp.async.commit_group;\n");

    for (int jt = 0; jt < njt; jt++) {
        int buf = jt & 1;
        if (jt + 1 < njt) {
            load_kv(jt + 1, buf ^ 1);
            asm volatile("cp.async.commit_group;\n");
            asm volatile("cp.async.wait_group 1;\n");
        } else {
            asm volatile("cp.async.wait_group 0;\n");
        }
        __syncthreads();

        const uint32_t* Kb = Ks + buf * 64 * KST;
        const uint32_t* Vb = Vs + buf * 128 * VSTW;
        int s0 = jt * 64;

        // ---- S = Q K^T ----
        float s_[8][4];
#pragma unroll
        for (int ns = 0; ns < 8; ns++)
#pragma unroll
            for (int j = 0; j < 4; j++) s_[ns][j] = 0.f;
#pragma unroll
        for (int hs = 0; hs < 8; hs++) {
#pragma unroll
            for (int ns = 0; ns < 8; ns++) {
                const uint32_t* p = Kb + (ns * 8 + lr) * KST + hs * 8 + lc;
                uint32_t bf[2] = {p[0], p[4]};
                mma16(s_[ns], qf[hs], bf);
            }
        }

        // ---- causal mask ----
        if (jt >= 2 * qt) {
#pragma unroll
            for (int ns = 0; ns < 8; ns++) {
                int col = s0 + ns * 8 + 2 * lc;
                if (col > row0)     s_[ns][0] = -1e30f;
                if (col + 1 > row0) s_[ns][1] = -1e30f;
                if (col > row0 + 8)     s_[ns][2] = -1e30f;
                if (col + 1 > row0 + 8) s_[ns][3] = -1e30f;
            }
        }

        // ---- online softmax (registers + quad shuffles) ----
        float mx0 = -1e30f, mx1 = -1e30f;
#pragma unroll
        for (int ns = 0; ns < 8; ns++) {
            mx0 = fmaxf(mx0, fmaxf(s_[ns][0], s_[ns][1]));
            mx1 = fmaxf(mx1, fmaxf(s_[ns][2], s_[ns][3]));
        }
        mx0 = fmaxf(mx0, __shfl_xor_sync(0xffffffffu, mx0, 1));
        mx0 = fmaxf(mx0, __shfl_xor_sync(0xffffffffu, mx0, 2));
        mx1 = fmaxf(mx1, __shfl_xor_sync(0xffffffffu, mx1, 1));
        mx1 = fmaxf(mx1, __shfl_xor_sync(0xffffffffu, mx1, 2));
        float mn0 = fmaxf(m_[0], mx0), mn1 = fmaxf(m_[1], mx1);
        float a0 = __expf(m_[0] - mn0), a1 = __expf(m_[1] - mn1);
        float sum0 = 0.f, sum1 = 0.f;
        uint32_t* Pw = Ps + warp * 16 * PSTW;
#pragma unroll
        for (int ns = 0; ns < 8; ns++) {
            float p0 = __expf(s_[ns][0] - mn0);
            float p1 = __expf(s_[ns][1] - mn0);
            float p2 = __expf(s_[ns][2] - mn1);
            float p3 = __expf(s_[ns][3] - mn1);
            sum0 += p0 + p1;
            sum1 += p2 + p3;
            Pw[lr * PSTW + ns * 4 + lc]       = f2h2(p0, p1);
            Pw[(lr + 8) * PSTW + ns * 4 + lc] = f2h2(p2, p3);
        }
        sum0 += __shfl_xor_sync(0xffffffffu, sum0, 1);
        sum0 += __shfl_xor_sync(0xffffffffu, sum0, 2);
        sum1 += __shfl_xor_sync(0xffffffffu, sum1, 1);
        sum1 += __shfl_xor_sync(0xffffffffu, sum1, 2);
        l_[0] = l_[0] * a0 + sum0;
        l_[1] = l_[1] * a1 + sum1;
        m_[0] = mn0; m_[1] = mn1;

#pragma unroll
        for (int ns = 0; ns < 16; ns++) {
            oacc[ns][0] *= a0; oacc[ns][1] *= a0;
            oacc[ns][2] *= a1; oacc[ns][3] *= a1;
        }
        __syncwarp();

        // ---- O += P V ----
#pragma unroll
        for (int ks = 0; ks < 4; ks++) {
            const uint32_t* pp = Pw + lr * PSTW + ks * 8 + lc;
            uint32_t af[4] = {pp[0], pp[8 * PSTW], pp[4], pp[8 * PSTW + 4]};
#pragma unroll
            for (int ns = 0; ns < 16; ns++) {
                const uint32_t* vp = Vb + (ns * 8 + lr) * VSTW + ks * 8 + lc;
                uint32_t bf[2] = {vp[0], vp[4]};
                mma16(oacc[ns], af, bf);
            }
        }
        __syncthreads();
    }

    // ---- epilogue: normalize, store fp16 (b,t,n,h) ----
    float inv0 = 1.f / l_[0], inv1 = 1.f / l_[1];
    size_t wb0 = ((size_t)((b * T_ + row0) * NH_ + n) << 6);
    size_t wb1 = ((size_t)((b * T_ + row0 + 8) * NH_ + n) << 6);
#pragma unroll
    for (int ns = 0; ns < 16; ns++) {
        o[wb0 + ns * 4 + lc] = f2h2(oacc[ns][0] * inv0, oacc[ns][1] * inv0);
        o[wb1 + ns * 4 + lc] = f2h2(oacc[ns][2] * inv1, oacc[ns][3] * inv1);
    }
}

// ---------------------------------------------------------------------------
extern "C" void kernel_launch(void* const* d_in, const int* in_sizes, int n_in,
                              void* d_out, int out_size) {
    const float* Xq   = (const float*)d_in[0];
    const float* Xkv  = (const float*)d_in[1];
    const int*   qpos = (const int*)  d_in[2];
    const int*   kpos = (const int*)  d_in[3];
    const float* Wq   = (const float*)d_in[4];
    const float* Wk   = (const float*)d_in[5];
    const float* Wv   = (const float*)d_in[6];
    const float* Wo   = (const float*)d_in[7];
    float* out = (float*)d_out;

    __half *xqh, *xkvh, *wqt, *wkt, *wvt, *wot, *qh, *kh, *vt, *attn;
    float *pq, *pk, *pv;
    cudaGetSymbolAddress((void**)&xqh,  g_xqh);
    cudaGetSymbolAddress((void**)&xkvh, g_xkvh);
    cudaGetSymbolAddress((void**)&wqt,  g_wqt);
    cudaGetSymbolAddress((void**)&wkt,  g_wkt);
    cudaGetSymbolAddress((void**)&wvt,  g_wvt);
    cudaGetSymbolAddress((void**)&wot,  g_wot);
    cudaGetSymbolAddress((void**)&pq,   g_q);
    cudaGetSymbolAddress((void**)&pk,   g_k);
    cudaGetSymbolAddress((void**)&pv,   g_v);
    cudaGetSymbolAddress((void**)&qh,   g_qh);
    cudaGetSymbolAddress((void**)&kh,   g_kh);
    cudaGetSymbolAddress((void**)&vt,   g_vt);
    cudaGetSymbolAddress((void**)&attn, g_attn);

    const int M = B_ * T_;  // 4096
    const int NHH = NH_ * H_, KHH = KH_ * H_;
    const float scale = 0.08838834764831845f; // 1/sqrt(128)

    // inputs -> fp16
    cvt16<<<(B_*T_*D_) / 1024, 256>>>(Xq,  (__half2*)xqh);
    cvt16<<<(B_*T_*D_) / 1024, 256>>>(Xkv, (__half2*)xkvh);
    // weights -> fp16 transposed
    tr16<<<dim3(NHH / 32, D_ / 32), 256>>>(Wq, wqt, D_, NHH);
    tr16<<<dim3(KHH / 32, D_ / 32), 256>>>(Wk, wkt, D_, KHH);
    tr16<<<dim3(KHH / 32, D_ / 32), 256>>>(Wv, wvt, D_, KHH);
    tr16<<<dim3(D_ / 32, NHH / 32), 256>>>(Wo, wot, NHH, D_);

    // projections
    gemm16<<<dim3(NHH / 128, M / 128), 256>>>(
        (const uint32_t*)xqh, (const uint32_t*)wqt, pq, M, NHH, D_);
    gemm16_kv<<<dim3(KHH / 128, M / 128, 2), 256>>>(
        (const uint32_t*)xkvh, (const uint32_t*)wkt, (const uint32_t*)wvt,
        pk, pv, M, KHH, D_);

    // rope (fp32 -> fp16), V transpose
    rope_q16<<<M, 64>>>(pq, qh, qpos, scale);
    rope_k16<<<M, 64>>>(pk, kh, kpos);
    trv<<<dim3(T_ / 32, H_ / 32, B_ * KH_), 256>>>(pv, vt);

    // flash attention (fp16 tensor core)
    cudaFuncSetAttribute(flash16,
                         cudaFuncAttributeMaxDynamicSharedMemorySize, FA5_SMEM);
    flash16<<<dim3(T_ / 128, NH_, B_), 256, FA5_SMEM>>>(
        (const uint32_t*)qh, (const uint32_t*)kh, (const uint32_t*)vt,
        (uint32_t*)attn);

    // output projection
    gemm16<<<dim3(D_ / 128, M / 128), 256>>>(
        (const uint32_t*)attn, (const uint32_t*)wot, out, M, D_, NHH);
}

// round 7
// speedup vs baseline: 1.7524x; 1.0243x over previous
#include <cuda_runtime.h>
#include <cuda_fp16.h>
#include <math.h>
#include <stdint.h>

#define B_  2
#define T_  2048
#define D_  2048
#define NH_ 16
#define KH_ 4
#define H_  128

// Scratch (allocation-free rule: __device__ globals)
__device__ __half g_xqh [B_*T_*D_];        // Xq  fp16
__device__ __half g_xkvh[B_*T_*D_];        // Xkv fp16
__device__ __half g_wqt [NH_*H_*D_];       // Wq^T  fp16 [NHH][D]
__device__ __half g_wkt [KH_*H_*D_];       // Wk^T  fp16 [KHH][D]
__device__ __half g_wvt [KH_*H_*D_];       // Wv^T  fp16 [KHH][D]
__device__ __half g_wot [D_*NH_*H_];       // Wo^T  fp16 [D][NHH]
__device__ float  g_q  [B_*T_*NH_*H_];     // q proj fp32
__device__ float  g_k  [B_*T_*KH_*H_];     // k proj fp32
__device__ float  g_v  [B_*T_*KH_*H_];     // v proj fp32
__device__ __half g_qh [B_*T_*NH_*H_];     // q rope'd, scaled, fp16 (b,t,n,h)
__device__ __half g_kh [B_*T_*KH_*H_];     // k rope'd fp16 (b,t,k,h)
__device__ __half g_vt [B_*KH_*H_*T_];     // v fp16 transposed (b,k,h,t)
__device__ __half g_attn[B_*T_*NH_*H_];    // attn out fp16 (b,t,n,h)

__device__ __forceinline__ uint32_t f2h2(float lo, float hi) {
    __half2 h = __floats2half2_rn(lo, hi);
    return *(uint32_t*)&h;
}

__device__ __forceinline__ void cpasync16(void* dst, const void* src) {
    uint32_t d = (uint32_t)__cvta_generic_to_shared(dst);
    asm volatile("cp.async.cg.shared.global [%0], [%1], 16;\n" :: "r"(d), "l"(src));
}

__device__ __forceinline__ void mma16(float* c, const uint32_t* a, const uint32_t* b) {
    asm volatile(
        "mma.sync.aligned.m16n8k16.row.col.f32.f16.f16.f32 "
        "{%0,%1,%2,%3}, {%4,%5,%6,%7}, {%8,%9}, {%0,%1,%2,%3};\n"
        : "+f"(c[0]), "+f"(c[1]), "+f"(c[2]), "+f"(c[3])
        : "r"(a[0]), "r"(a[1]), "r"(a[2]), "r"(a[3]),
          "r"(b[0]), "r"(b[1]));
}

// ---------------------------------------------------------------------------
// Aux kernels: cvt fp32->fp16, transposes
// ---------------------------------------------------------------------------
__global__ void cvt16(const float* __restrict__ s, __half2* __restrict__ d) {
    int i = blockIdx.x * 256 + threadIdx.x;
    float4 a = ((const float4*)s)[i];
    d[2*i]   = __floats2half2_rn(a.x, a.y);
    d[2*i+1] = __floats2half2_rn(a.z, a.w);
}

// transpose + cvt: src fp32 [R][C] -> dst fp16 [C][R]; grid (C/32, R/32), 256 thr
__global__ void tr16(const float* __restrict__ src, __half* __restrict__ dst,
                     int R, int C) {
    __shared__ float tile[32][33];
    int c0 = blockIdx.x * 32, r0 = blockIdx.y * 32;
    int tx = threadIdx.x & 31, ty = threadIdx.x >> 5;
#pragma unroll
    for (int i = 0; i < 32; i += 8)
        tile[ty + i][tx] = src[(size_t)(r0 + ty + i) * C + c0 + tx];
    __syncthreads();
#pragma unroll
    for (int i = 0; i < 32; i += 8)
        dst[(size_t)(c0 + ty + i) * R + r0 + tx] = __float2half_rn(tile[tx][ty + i]);
}

// V transpose: fp32 (b,t,kh,h) -> fp16 (b,kh,h,t); grid (T/32, H/32, B*KH)
__global__ void trv(const float* __restrict__ v, __half* __restrict__ vt) {
    __shared__ float tile[32][33];
    int bk = blockIdx.z, b = bk >> 2, kh = bk & 3;
    int t0 = blockIdx.x * 32, h0 = blockIdx.y * 32;
    int tx = threadIdx.x & 31, ty = threadIdx.x >> 5;
#pragma unroll
    for (int i = 0; i < 32; i += 8)
        tile[ty + i][tx] =
            v[(((size_t)(b * T_ + t0 + ty + i)) * KH_ + kh) * H_ + h0 + tx];
    __syncthreads();
#pragma unroll
    for (int i = 0; i < 32; i += 8)
        vt[((size_t)(b * KH_ + kh) * H_ + h0 + ty + i) * T_ + t0 + tx] =
            __float2half_rn(tile[tx][ty + i]);
}

// ---------------------------------------------------------------------------
// RoPE: fp32 in -> fp16 out (q also scaled)
// ---------------------------------------------------------------------------
__global__ void rope_q16(const float* __restrict__ x, __half* __restrict__ y,
                         const int* __restrict__ pos, float scale) {
    int token = blockIdx.x;
    int i = threadIdx.x;  // 0..63
    double ts = exp(((double)i / 64.0) * 9.210340371976182736);
    float p = (float)pos[token];
    float angf = p / (float)ts;
    double s_, c_;
    sincos((double)angf, &s_, &c_);
    float s = (float)s_, c = (float)c_;
    const float* base = x + (size_t)token * NH_ * H_;
    __half* dst = y + (size_t)token * NH_ * H_;
#pragma unroll 4
    for (int n = 0; n < NH_; n++) {
        float x1 = base[n * H_ + i];
        float x2 = base[n * H_ + i + 64];
        dst[n * H_ + i]      = __float2half_rn((x1 * c - x2 * s) * scale);
        dst[n * H_ + i + 64] = __float2half_rn((x2 * c + x1 * s) * scale);
    }
}

__global__ void rope_k16(const float* __restrict__ x, __half* __restrict__ y,
                         const int* __restrict__ pos) {
    int token = blockIdx.x;
    int i = threadIdx.x;
    double ts = exp(((double)i / 64.0) * 9.210340371976182736);
    float p = (float)pos[token];
    float angf = p / (float)ts;
    double s_, c_;
    sincos((double)angf, &s_, &c_);
    float s = (float)s_, c = (float)c_;
    const float* base = x + (size_t)token * KH_ * H_;
    __half* dst = y + (size_t)token * KH_ * H_;
#pragma unroll
    for (int n = 0; n < KH_; n++) {
        float x1 = base[n * H_ + i];
        float x2 = base[n * H_ + i + 64];
        dst[n * H_ + i]      = __float2half_rn(x1 * c - x2 * s);
        dst[n * H_ + i + 64] = __float2half_rn(x2 * c + x1 * s);
    }
}

// ---------------------------------------------------------------------------
// FP16 tensor-core GEMM: C[M,Nc]fp32 = A[M,Kd]fp16 @ Bt[Nc,Kd]fp16^T
// 128x128 tile, k-tile 32, m16n8k16, cp.async double buffered.
// __launch_bounds__(256, 2) -> <=128 regs -> 2 blocks/SM for latency hiding.
// ---------------------------------------------------------------------------
#define GST 20

__device__ __forceinline__
void gemm16_body(const uint32_t* __restrict__ A, const uint32_t* __restrict__ Bt,
                 float* __restrict__ C, int M, int Nc, int Kd) {
    __shared__ uint32_t As[2][128 * GST];
    __shared__ uint32_t Bs[2][128 * GST];
    int tid  = threadIdx.x;
    int brow = blockIdx.y * 128, bcol = blockIdx.x * 128;
    int warp = tid >> 5, lane = tid & 31;
    int mw = (warp >> 2) * 64, nw = (warp & 3) * 32;
    int lr = lane >> 2, lc = lane & 3;
    int KW = Kd >> 1;  // words per row

    float acc[4][4][4];
#pragma unroll
    for (int mi = 0; mi < 4; mi++)
#pragma unroll
        for (int ni = 0; ni < 4; ni++)
#pragma unroll
            for (int j = 0; j < 4; j++) acc[mi][ni][j] = 0.f;

    const int nkt = Kd >> 5;

    auto load_stage = [&](int kt, int buf) {
        int kw0 = kt * 16;
#pragma unroll
        for (int u = 0; u < 2; u++) {
            int c = tid + 256 * u;
            int row = c >> 2, w4 = (c & 3) * 4;
            cpasync16(&As[buf][row * GST + w4],
                      &A[(size_t)(brow + row) * KW + kw0 + w4]);
            cpasync16(&Bs[buf][row * GST + w4],
                      &Bt[(size_t)(bcol + row) * KW + kw0 + w4]);
        }
    };

    load_stage(0, 0);
    asm volatile("cp.async.commit_group;\n");

    for (int kt = 0; kt < nkt; kt++) {
        int buf = kt & 1;
        if (kt + 1 < nkt) {
            load_stage(kt + 1, buf ^ 1);
            asm volatile("cp.async.commit_group;\n");
            asm volatile("cp.async.wait_group 1;\n");
        } else {
            asm volatile("cp.async.wait_group 0;\n");
        }
        __syncthreads();

#pragma unroll
        for (int ks = 0; ks < 2; ks++) {
            uint32_t af[4][4], bf[4][2];
#pragma unroll
            for (int mi = 0; mi < 4; mi++) {
                const uint32_t* p = &As[buf][(mw + mi * 16 + lr) * GST + ks * 8 + lc];
                af[mi][0] = p[0];
                af[mi][1] = p[8 * GST];
                af[mi][2] = p[4];
                af[mi][3] = p[8 * GST + 4];
            }
#pragma unroll
            for (int ni = 0; ni < 4; ni++) {
                const uint32_t* p = &Bs[buf][(nw + ni * 8 + lr) * GST + ks * 8 + lc];
                bf[ni][0] = p[0];
                bf[ni][1] = p[4];
            }
#pragma unroll
            for (int mi = 0; mi < 4; mi++)
#pragma unroll
                for (int ni = 0; ni < 4; ni++)
                    mma16(acc[mi][ni], af[mi], bf[ni]);
        }
        __syncthreads();
    }

#pragma unroll
    for (int mi = 0; mi < 4; mi++) {
#pragma unroll
        for (int ni = 0; ni < 4; ni++) {
            int r0 = brow + mw + mi * 16 + lr;
            int cc = bcol + nw + ni * 8 + lc * 2;
            *(float2*)&C[(size_t)r0 * Nc + cc] =
                make_float2(acc[mi][ni][0], acc[mi][ni][1]);
            *(float2*)&C[(size_t)(r0 + 8) * Nc + cc] =
                make_float2(acc[mi][ni][2], acc[mi][ni][3]);
        }
    }
}

__global__ __launch_bounds__(256, 2)
void gemm16(const uint32_t* __restrict__ A, const uint32_t* __restrict__ Bt,
            float* __restrict__ C, int M, int Nc, int Kd) {
    gemm16_body(A, Bt, C, M, Nc, Kd);
}

__global__ __launch_bounds__(256, 2)
void gemm16_kv(const uint32_t* __restrict__ A,
               const uint32_t* __restrict__ B0, const uint32_t* __restrict__ B1,
               float* __restrict__ C0, float* __restrict__ C1,
               int M, int Nc, int Kd) {
    gemm16_body(A, blockIdx.z ? B1 : B0, blockIdx.z ? C1 : C0, M, Nc, Kd);
}

// ---------------------------------------------------------------------------
// FP16 tensor-core flash attention, causal, GQA.
// Q tile 128 (8 warps x m16), KV tile 128, m16n8k16, cp.async double buffer.
// Ks [2][128][68w], Vs(=V^T) [2][128][68w], Ps [8][16][68w].
// ---------------------------------------------------------------------------
#define KST  68
#define VSTW 68
#define PSTW 68
#define FA6_SMEM ((2*128*KST + 2*128*VSTW + 8*16*PSTW) * 4)

__global__ __launch_bounds__(256, 1)
void flash16(const uint32_t* __restrict__ qh, const uint32_t* __restrict__ kk,
             const uint32_t* __restrict__ vt, uint32_t* __restrict__ o) {
    extern __shared__ uint32_t sm_u[];
    uint32_t* Ks = sm_u;                     // [2][128*KST]
    uint32_t* Vs = Ks + 2 * 128 * KST;       // [2][128*VSTW]
    uint32_t* Ps = Vs + 2 * 128 * VSTW;      // [8][16*PSTW]

    int qt = (int)gridDim.x - 1 - (int)blockIdx.x;  // big tiles first
    int n  = blockIdx.y;
    int b  = blockIdx.z;
    int khd = n >> 2;
    int tid = threadIdx.x, warp = tid >> 5, lane = tid & 31;
    int lr = lane >> 2, lc = lane & 3;
    int q0 = qt * 128;

    // ---- Q fragments: stage 64 rows at a time into Ks[0], frag-load ----
    uint32_t qf[8][4];
#pragma unroll
    for (int pass = 0; pass < 2; pass++) {
#pragma unroll
        for (int u = 0; u < 4; u++) {
            int f = tid + 256 * u;
            int r = f >> 4, w4 = (f & 15) * 4;
            *(uint4*)(Ks + r * KST + w4) = *(const uint4*)(qh +
                ((size_t)((b * T_ + q0 + pass * 64 + r) * NH_ + n) << 6) + w4);
        }
        __syncthreads();
        if ((warp >> 2) == pass) {
            int mr = (warp & 3) * 16;
#pragma unroll
            for (int hs = 0; hs < 8; hs++) {
                const uint32_t* p = Ks + (mr + lr) * KST + hs * 8 + lc;
                qf[hs][0] = p[0];
                qf[hs][1] = p[8 * KST];
                qf[hs][2] = p[4];
                qf[hs][3] = p[8 * KST + 4];
            }
        }
        __syncthreads();
    }

    float m_[2] = {-1e30f, -1e30f};
    float l_[2] = {0.f, 0.f};
    float oacc[16][4];
#pragma unroll
    for (int ns = 0; ns < 16; ns++)
#pragma unroll
        for (int j = 0; j < 4; j++) oacc[ns][j] = 0.f;

    int row0 = q0 + warp * 16 + lr;
    int njt = qt + 1;

    auto load_kv = [&](int jt, int bufsel) {
        int s0 = jt * 128;
        uint32_t* Kd = Ks + bufsel * 128 * KST;
        uint32_t* Vd = Vs + bufsel * 128 * VSTW;
#pragma unroll
        for (int u = 0; u < 8; u++) {
            int f = tid + 256 * u;
            int r = f >> 4, w4 = (f & 15) * 4;
            cpasync16(Kd + r * KST + w4,
                      kk + ((size_t)((b * T_ + s0 + r) * KH_ + khd) << 6) + w4);
            cpasync16(Vd + r * VSTW + w4,
                      vt + ((((size_t)(b * KH_ + khd) * H_ + r) * T_ + s0) >> 1) + w4);
        }
    };

    load_kv(0, 0);
    asm volatile("cp.async.commit_group;\n");

    for (int jt = 0; jt < njt; jt++) {
        int buf = jt & 1;
        if (jt + 1 < njt) {
            load_kv(jt + 1, buf ^ 1);
            asm volatile("cp.async.commit_group;\n");
            asm volatile("cp.async.wait_group 1;\n");
        } else {
            asm volatile("cp.async.wait_group 0;\n");
        }
        __syncthreads();

        const uint32_t* Kb = Ks + buf * 128 * KST;
        const uint32_t* Vb = Vs + buf * 128 * VSTW;
        int s0 = jt * 128;

        // ---- S = Q K^T (16 n-frags x 8 k-steps) ----
        float s_[16][4];
#pragma unroll
        for (int ns = 0; ns < 16; ns++)
#pragma unroll
            for (int j = 0; j < 4; j++) s_[ns][j] = 0.f;
#pragma unroll
        for (int hs = 0; hs < 8; hs++) {
#pragma unroll
            for (int ns = 0; ns < 16; ns++) {
                const uint32_t* p = Kb + (ns * 8 + lr) * KST + hs * 8 + lc;
                uint32_t bf[2] = {p[0], p[4]};
                mma16(s_[ns], qf[hs], bf);
            }
        }

        // ---- causal mask (only the diagonal tile crosses) ----
        if (jt == qt) {
#pragma unroll
            for (int ns = 0; ns < 16; ns++) {
                int col = s0 + ns * 8 + 2 * lc;
                if (col > row0)     s_[ns][0] = -1e30f;
                if (col + 1 > row0) s_[ns][1] = -1e30f;
                if (col > row0 + 8)     s_[ns][2] = -1e30f;
                if (col + 1 > row0 + 8) s_[ns][3] = -1e30f;
            }
        }

        // ---- online softmax (registers + quad shuffles) ----
        float mx0 = -1e30f, mx1 = -1e30f;
#pragma unroll
        for (int ns = 0; ns < 16; ns++) {
            mx0 = fmaxf(mx0, fmaxf(s_[ns][0], s_[ns][1]));
            mx1 = fmaxf(mx1, fmaxf(s_[ns][2], s_[ns][3]));
        }
        mx0 = fmaxf(mx0, __shfl_xor_sync(0xffffffffu, mx0, 1));
        mx0 = fmaxf(mx0, __shfl_xor_sync(0xffffffffu, mx0, 2));
        mx1 = fmaxf(mx1, __shfl_xor_sync(0xffffffffu, mx1, 1));
        mx1 = fmaxf(mx1, __shfl_xor_sync(0xffffffffu, mx1, 2));
        float mn0 = fmaxf(m_[0], mx0), mn1 = fmaxf(m_[1], mx1);
        float a0 = __expf(m_[0] - mn0), a1 = __expf(m_[1] - mn1);
        float sum0 = 0.f, sum1 = 0.f;
        uint32_t* Pw = Ps + warp * 16 * PSTW;
#pragma unroll
        for (int ns = 0; ns < 16; ns++) {
            float p0 = __expf(s_[ns][0] - mn0);
            float p1 = __expf(s_[ns][1] - mn0);
            float p2 = __expf(s_[ns][2] - mn1);
            float p3 = __expf(s_[ns][3] - mn1);
            sum0 += p0 + p1;
            sum1 += p2 + p3;
            Pw[lr * PSTW + ns * 4 + lc]       = f2h2(p0, p1);
            Pw[(lr + 8) * PSTW + ns * 4 + lc] = f2h2(p2, p3);
        }
        sum0 += __shfl_xor_sync(0xffffffffu, sum0, 1);
        sum0 += __shfl_xor_sync(0xffffffffu, sum0, 2);
        sum1 += __shfl_xor_sync(0xffffffffu, sum1, 1);
        sum1 += __shfl_xor_sync(0xffffffffu, sum1, 2);
        l_[0] = l_[0] * a0 + sum0;
        l_[1] = l_[1] * a1 + sum1;
        m_[0] = mn0; m_[1] = mn1;

#pragma unroll
        for (int ns = 0; ns < 16; ns++) {
            oacc[ns][0] *= a0; oacc[ns][1] *= a0;
            oacc[ns][2] *= a1; oacc[ns][3] *= a1;
        }
        __syncwarp();

        // ---- O += P V (8 k-steps over 128 kv) ----
#pragma unroll
        for (int ks = 0; ks < 8; ks++) {
            const uint32_t* pp = Pw + lr * PSTW + ks * 8 + lc;
            uint32_t af[4] = {pp[0], pp[8 * PSTW], pp[4], pp[8 * PSTW + 4]};
#pragma unroll
            for (int ns = 0; ns < 16; ns++) {
                const uint32_t* vp = Vb + (ns * 8 + lr) * VSTW + ks * 8 + lc;
                uint32_t bf[2] = {vp[0], vp[4]};
                mma16(oacc[ns], af, bf);
            }
        }
        __syncthreads();
    }

    // ---- epilogue: normalize, store fp16 (b,t,n,h) ----
    float inv0 = 1.f / l_[0], inv1 = 1.f / l_[1];
    size_t wb0 = ((size_t)((b * T_ + row0) * NH_ + n) << 6);
    size_t wb1 = ((size_t)((b * T_ + row0 + 8) * NH_ + n) << 6);
#pragma unroll
    for (int ns = 0; ns < 16; ns++) {
        o[wb0 + ns * 4 + lc] = f2h2(oacc[ns][0] * inv0, oacc[ns][1] * inv0);
        o[wb1 + ns * 4 + lc] = f2h2(oacc[ns][2] * inv1, oacc[ns][3] * inv1);
    }
}

// ---------------------------------------------------------------------------
extern "C" void kernel_launch(void* const* d_in, const int* in_sizes, int n_in,
                              void* d_out, int out_size) {
    const float* Xq   = (const float*)d_in[0];
    const float* Xkv  = (const float*)d_in[1];
    const int*   qpos = (const int*)  d_in[2];
    const int*   kpos = (const int*)  d_in[3];
    const float* Wq   = (const float*)d_in[4];
    const float* Wk   = (const float*)d_in[5];
    const float* Wv   = (const float*)d_in[6];
    const float* Wo   = (const float*)d_in[7];
    float* out = (float*)d_out;

    __half *xqh, *xkvh, *wqt, *wkt, *wvt, *wot, *qh, *kh, *vt, *attn;
    float *pq, *pk, *pv;
    cudaGetSymbolAddress((void**)&xqh,  g_xqh);
    cudaGetSymbolAddress((void**)&xkvh, g_xkvh);
    cudaGetSymbolAddress((void**)&wqt,  g_wqt);
    cudaGetSymbolAddress((void**)&wkt,  g_wkt);
    cudaGetSymbolAddress((void**)&wvt,  g_wvt);
    cudaGetSymbolAddress((void**)&wot,  g_wot);
    cudaGetSymbolAddress((void**)&pq,   g_q);
    cudaGetSymbolAddress((void**)&pk,   g_k);
    cudaGetSymbolAddress((void**)&pv,   g_v);
    cudaGetSymbolAddress((void**)&qh,   g_qh);
    cudaGetSymbolAddress((void**)&kh,   g_kh);
    cudaGetSymbolAddress((void**)&vt,   g_vt);
    cudaGetSymbolAddress((void**)&attn, g_attn);

    const int M = B_ * T_;  // 4096
    const int NHH = NH_ * H_, KHH = KH_ * H_;
    const float scale = 0.08838834764831845f; // 1/sqrt(128)

    // inputs -> fp16
    cvt16<<<(B_*T_*D_) / 1024, 256>>>(Xq,  (__half2*)xqh);
    cvt16<<<(B_*T_*D_) / 1024, 256>>>(Xkv, (__half2*)xkvh);
    // weights -> fp16 transposed
    tr16<<<dim3(NHH / 32, D_ / 32), 256>>>(Wq, wqt, D_, NHH);
    tr16<<<dim3(KHH / 32, D_ / 32), 256>>>(Wk, wkt, D_, KHH);
    tr16<<<dim3(KHH / 32, D_ / 32), 256>>>(Wv, wvt, D_, KHH);
    tr16<<<dim3(D_ / 32, NHH / 32), 256>>>(Wo, wot, NHH, D_);

    // projections
    gemm16<<<dim3(NHH / 128, M / 128), 256>>>(
        (const uint32_t*)xqh, (const uint32_t*)wqt, pq, M, NHH, D_);
    gemm16_kv<<<dim3(KHH / 128, M / 128, 2), 256>>>(
        (const uint32_t*)xkvh, (const uint32_t*)wkt, (const uint32_t*)wvt,
        pk, pv, M, KHH, D_);

    // rope (fp32 -> fp16), V transpose
    rope_q16<<<M, 64>>>(pq, qh, qpos, scale);
    rope_k16<<<M, 64>>>(pk, kh, kpos);
    trv<<<dim3(T_ / 32, H_ / 32, B_ * KH_), 256>>>(pv, vt);

    // flash attention (fp16 tensor core, KV tile 128)
    cudaFuncSetAttribute(flash16,
                         cudaFuncAttributeMaxDynamicSharedMemorySize, FA6_SMEM);
    flash16<<<dim3(T_ / 128, NH_, B_), 256, FA6_SMEM>>>(
        (const uint32_t*)qh, (const uint32_t*)kh, (const uint32_t*)vt,
        (uint32_t*)attn);

    // output projection
    gemm16<<<dim3(D_ / 128, M / 128), 256>>>(
        (const uint32_t*)attn, (const uint32_t*)wot, out, M, D_, NHH);
}